// round 2
// baseline (speedup 1.0000x reference)
#include <cuda_runtime.h>
#include <math.h>
#include <stdint.h>

#define T_STEPS 20
#define BATCH   64
#define PIX     196
#define ENC_C   256
#define ATT_D   512
#define DEC_D   512
#define EMB_D   512
#define VOCAB   30000
#define GATES   2048

// ---------------- device scratch (static; no allocations allowed) ----------
__device__ float g_feats[BATCH * PIX * ENC_C];      // [b][p][c]
__device__ float g_enc_att[BATCH * PIX * ATT_D];    // [b][p][a]
__device__ float g_E[T_STEPS * BATCH * EMB_D];      // row m = t*64+b
__device__ float g_xg[T_STEPS * BATCH * GATES];     // emb part of gates (+biases)
__device__ float g_dec[BATCH * ATT_D];              // h @ W_dec + b_dec
__device__ float g_gates[BATCH * GATES];
__device__ float g_h[2][BATCH * DEC_D];             // double-buffered hidden
__device__ float g_c[BATCH * DEC_D];
__device__ float g_ctx[BATCH * ENC_C];
__device__ float g_Hall[T_STEPS * BATCH * DEC_D];   // all h_t, row m = t*64+b
__device__ float g_bias2[GATES];                    // b_ih + b_hh
__device__ int   g_cap64;

// ---------------- f32x2 helpers --------------------------------------------
__device__ __forceinline__ unsigned long long pk2(float lo, float hi) {
    unsigned long long r;
    asm("mov.b64 %0, {%1, %2};" : "=l"(r) : "f"(lo), "f"(hi));
    return r;
}
__device__ __forceinline__ void fma2(unsigned long long &d, unsigned long long a,
                                     unsigned long long b) {
    asm("fma.rn.f32x2 %0, %1, %2, %0;" : "+l"(d) : "l"(a), "l"(b));
}
__device__ __forceinline__ float2 upk(unsigned long long v) {
    float2 r;
    asm("mov.b64 {%0, %1}, %2;" : "=f"(r.x), "=f"(r.y) : "l"(v));
    return r;
}
__device__ __forceinline__ float sigmoidf_(float x) { return 1.f / (1.f + expf(-x)); }

// ---------------- init ------------------------------------------------------
__global__ void k_init(const float* __restrict__ b_ih, const float* __restrict__ b_hh,
                       const void* __restrict__ caps) {
    int idx = blockIdx.x * 256 + threadIdx.x;
    if (idx < BATCH * DEC_D) g_h[0][idx] = 0.f;
    else if (idx < 2 * BATCH * DEC_D) g_c[idx - BATCH * DEC_D] = 0.f;
    else if (idx < 2 * BATCH * DEC_D + GATES) {
        int n = idx - 2 * BATCH * DEC_D;
        g_bias2[n] = b_ih[n] + b_hh[n];
    }
    if (blockIdx.x == 0 && threadIdx.x == 0) {
        // int64 captions (<30000) have zero odd 32-bit words; int32 doesn't.
        const int* ci = (const int*)caps;
        int all0 = 1;
        for (int i = 0; i < 64; i++) if (ci[2 * i + 1] != 0) { all0 = 0; break; }
        g_cap64 = all0;
    }
}

// ---------------- transpose [b][c][p] -> feats [b][p][c] -------------------
__global__ void k_transpose(const float* __restrict__ in) {
    __shared__ float tile[32][33];
    int b  = blockIdx.z;
    int p0 = blockIdx.x * 32;
    int c0 = blockIdx.y * 32;
    int tx = threadIdx.x, ty = threadIdx.y;
    const float* src = in + ((size_t)b * ENC_C + c0) * PIX + p0;
#pragma unroll
    for (int i = 0; i < 4; i++) {
        int c = ty + i * 8;
        if (p0 + tx < PIX) tile[c][tx] = src[c * PIX + tx];
    }
    __syncthreads();
    float* dst = g_feats + (size_t)b * PIX * ENC_C;
#pragma unroll
    for (int i = 0; i < 4; i++) {
        int p = ty + i * 8;
        if (p0 + p < PIX) dst[(size_t)(p0 + p) * ENC_C + c0 + tx] = tile[tx][p];
    }
}

// ---------------- embedding gather -----------------------------------------
__global__ void k_gather(const void* __restrict__ caps, const float* __restrict__ emb) {
    int m = blockIdx.x;
    int tt = m >> 6, b = m & 63;
    long long cap;
    if (g_cap64) cap = ((const long long*)caps)[b * T_STEPS + tt];
    else         cap = ((const int*)caps)[b * T_STEPS + tt];
    if ((unsigned long long)cap >= (unsigned long long)VOCAB) cap = 0;
    const float4* src = (const float4*)(emb + (size_t)cap * EMB_D);
    float4* dst = (float4*)(g_E + (size_t)m * EMB_D);
    dst[threadIdx.x] = src[threadIdx.x];
}

// ---------------- generic f32x2 GEMM: C = A @ op(B) + bias -----------------
// 128(M) x 64(N) tile, KT=16, 256 threads, 8x4 per thread as f32x2 pairs.
template <bool TRANSB, bool REMAP>
__global__ __launch_bounds__(256, 2)
void k_gemm(const float* __restrict__ A, int lda,
            const float* __restrict__ B, int ldb,
            const float* __restrict__ bias,
            float* __restrict__ C, int ldc,
            int M, int N, int K) {
    __shared__ float As[16][132];   // [k][m]
    __shared__ float Bs[16][68];    // [k][n]
    const int t  = threadIdx.x;
    const int tx = t & 15, ty = t >> 4;
    const int m0 = blockIdx.y * 128, n0 = blockIdx.x * 64;

    unsigned long long acc[4][4];
#pragma unroll
    for (int i = 0; i < 4; i++)
#pragma unroll
        for (int j = 0; j < 4; j++) acc[i][j] = 0ull;

    for (int k0 = 0; k0 < K; k0 += 16) {
        {   // A tile
            int i = t >> 1, kh = (t & 1) << 3;
            int m = m0 + i;
            float4 v0 = {0,0,0,0}, v1 = {0,0,0,0};
            if (m < M) {
                const float4* p = (const float4*)(A + (size_t)m * lda + k0 + kh);
                v0 = p[0]; v1 = p[1];
            }
            As[kh+0][i]=v0.x; As[kh+1][i]=v0.y; As[kh+2][i]=v0.z; As[kh+3][i]=v0.w;
            As[kh+4][i]=v1.x; As[kh+5][i]=v1.y; As[kh+6][i]=v1.z; As[kh+7][i]=v1.w;
        }
        if (!TRANSB) {
            int kk = t >> 4, nq = (t & 15) << 2;
            float4 v = {0,0,0,0};
            if (n0 + nq + 4 <= N)
                v = *(const float4*)(B + (size_t)(k0 + kk) * ldb + n0 + nq);
            Bs[kk][nq]=v.x; Bs[kk][nq+1]=v.y; Bs[kk][nq+2]=v.z; Bs[kk][nq+3]=v.w;
        } else {
            int n = t >> 2, kq = (t & 3) << 2;
            float4 v = {0,0,0,0};
            if (n0 + n < N)
                v = *(const float4*)(B + (size_t)(n0 + n) * ldb + k0 + kq);
            Bs[kq][n]=v.x; Bs[kq+1][n]=v.y; Bs[kq+2][n]=v.z; Bs[kq+3][n]=v.w;
        }
        __syncthreads();
#pragma unroll
        for (int kk = 0; kk < 16; kk++) {
            unsigned long long a2[4];
            a2[0] = *(const unsigned long long*)&As[kk][ty*8+0];
            a2[1] = *(const unsigned long long*)&As[kk][ty*8+2];
            a2[2] = *(const unsigned long long*)&As[kk][ty*8+4];
            a2[3] = *(const unsigned long long*)&As[kk][ty*8+6];
            float4 b4 = *(const float4*)&Bs[kk][tx*4];
            unsigned long long b2[4] = {pk2(b4.x,b4.x), pk2(b4.y,b4.y),
                                        pk2(b4.z,b4.z), pk2(b4.w,b4.w)};
#pragma unroll
            for (int i = 0; i < 4; i++)
#pragma unroll
                for (int j = 0; j < 4; j++) fma2(acc[i][j], a2[i], b2[j]);
        }
        __syncthreads();
    }
#pragma unroll
    for (int j = 0; j < 4; j++) {
        int col = n0 + tx * 4 + j;
        if (col >= N) continue;
        float bv = bias ? bias[col] : 0.f;
#pragma unroll
        for (int i = 0; i < 4; i++) {
            float2 v = upk(acc[i][j]);
            int m = m0 + ty * 8 + i * 2;
            if (m < M) {
                int r = REMAP ? ((m & 63) * T_STEPS + (m >> 6)) : m;
                C[(size_t)r * ldc + col] = v.x + bv;
            }
            if (m + 1 < M) {
                int m1 = m + 1;
                int r = REMAP ? ((m1 & 63) * T_STEPS + (m1 >> 6)) : m1;
                C[(size_t)r * ldc + col] = v.y + bv;
            }
        }
    }
}

// ---------------- per-step: dec_att = h @ W_dec + b_dec --------------------
// W_dec is [K=512][N=512] (NN). 32 blocks x 16 N-cols, all 64 batch rows.
__global__ __launch_bounds__(256) void k_dec(const float* __restrict__ W_dec,
                                             const float* __restrict__ b_dec, int t) {
    __shared__ float hs[64][68];
    __shared__ float ws[64][17];
    int tid = threadIdx.x, n0 = blockIdx.x * 16;
    const float* hb = g_h[t & 1];
    int lb = tid & 63, kq = (tid >> 6) * 16;      // hs loader
    int wk = tid >> 2, wq = (tid & 3) * 4;        // ws loader (64 k x 16 n)
    int nl = tid & 15, bq = tid >> 4;             // compute
    unsigned long long acc0 = 0ull, acc1 = 0ull;
    for (int c = 0; c < 8; c++) {
        int k0 = c * 64;
#pragma unroll
        for (int j = 0; j < 4; j++) {
            float4 v = *(const float4*)(hb + lb * 512 + k0 + kq + j * 4);
            hs[kq+j*4+0][lb]=v.x; hs[kq+j*4+1][lb]=v.y;
            hs[kq+j*4+2][lb]=v.z; hs[kq+j*4+3][lb]=v.w;
        }
        {
            float4 v = *(const float4*)(W_dec + (size_t)(k0 + wk) * 512 + n0 + wq);
            ws[wk][wq]=v.x; ws[wk][wq+1]=v.y; ws[wk][wq+2]=v.z; ws[wk][wq+3]=v.w;
        }
        __syncthreads();
#pragma unroll 16
        for (int kk = 0; kk < 64; kk++) {
            float w = ws[kk][nl];
            unsigned long long w2 = pk2(w, w);
            fma2(acc0, *(const unsigned long long*)&hs[kk][bq*4],   w2);
            fma2(acc1, *(const unsigned long long*)&hs[kk][bq*4+2], w2);
        }
        __syncthreads();
    }
    int n = n0 + nl; float bv = b_dec[n];
    float2 a = upk(acc0), b2 = upk(acc1);
    g_dec[(bq*4+0)*512+n] = a.x + bv;
    g_dec[(bq*4+1)*512+n] = a.y + bv;
    g_dec[(bq*4+2)*512+n] = b2.x + bv;
    g_dec[(bq*4+3)*512+n] = b2.y + bv;
}

// ---------------- per-step: fused attention scores/softmax/context ---------
__global__ __launch_bounds__(256) void k_att(const float* __restrict__ W_full, int t) {
    __shared__ float dec_s[512], wf_s[512], sc_s[224];
    __shared__ float red[8];
    int b = blockIdx.x, tid = threadIdx.x;
    dec_s[tid] = g_dec[b*512+tid]; dec_s[tid+256] = g_dec[b*512+tid+256];
    wf_s[tid] = W_full[tid]; wf_s[tid+256] = W_full[tid+256];
    __syncthreads();
    int wp = tid >> 5, lane = tid & 31;
    for (int p = wp; p < PIX; p += 8) {
        const float* ea = g_enc_att + ((size_t)b * PIX + p) * ATT_D;
        float s = 0.f;
#pragma unroll 4
        for (int a = lane; a < 512; a += 32)
            s = fmaf(fmaxf(ea[a] + dec_s[a], 0.f), wf_s[a], s);
#pragma unroll
        for (int o = 16; o; o >>= 1) s += __shfl_xor_sync(0xffffffffu, s, o);
        if (!lane) sc_s[p] = s;      // +b_full omitted: softmax shift-invariant
    }
    __syncthreads();
    float v = (tid < PIX) ? sc_s[tid] : -1e30f;
    float mx = v;
#pragma unroll
    for (int o = 16; o; o >>= 1) mx = fmaxf(mx, __shfl_xor_sync(0xffffffffu, mx, o));
    if (!lane) red[wp] = mx;
    __syncthreads();
    if (tid == 0) { float m = red[0]; for (int i = 1; i < 8; i++) m = fmaxf(m, red[i]); red[0] = m; }
    __syncthreads();
    float e = (tid < PIX) ? expf(v - red[0]) : 0.f;
    float ss = e;
#pragma unroll
    for (int o = 16; o; o >>= 1) ss += __shfl_xor_sync(0xffffffffu, ss, o);
    __syncthreads();                  // all reads of red[0] (max) done
    if (!lane) red[wp] = ss;
    __syncthreads();
    if (tid == 0) { float s = 0.f; for (int i = 0; i < 8; i++) s += red[i]; red[0] = s; }
    __syncthreads();
    if (tid < PIX) sc_s[tid] = e / red[0];
    __syncthreads();
    const float* fb = g_feats + (size_t)b * PIX * ENC_C;
    float cx = 0.f;
#pragma unroll 4
    for (int p = 0; p < PIX; p++) cx = fmaf(sc_s[p], fb[p * ENC_C + tid], cx);
    g_ctx[b * ENC_C + tid] = cx;
}

// ---------------- per-step: gates = xg + h@W_hh^T + ctx@W_ih[:,512:]^T -----
// 128 blocks x 16 gate-cols; K = 768 (512 from h, 256 from ctx).
__global__ __launch_bounds__(256) void k_gates(const float* __restrict__ W_hh,
                                               const float* __restrict__ W_ih, int t) {
    __shared__ float hs[64][68];
    __shared__ float ws[64][17];
    int tid = threadIdx.x, n0 = blockIdx.x * 16;
    const float* hb = g_h[t & 1];
    int lb = tid & 63, kq = (tid >> 6) * 16;      // hs loader
    int wn = tid >> 4, wq = (tid & 15) * 4;       // ws loader (16 n x 64 k, NT)
    int nl = tid & 15, bq = tid >> 4;             // compute
    unsigned long long acc0 = 0ull, acc1 = 0ull;
    for (int c = 0; c < 12; c++) {
        int k0 = c * 64;
        if (k0 < 512) {
#pragma unroll
            for (int j = 0; j < 4; j++) {
                float4 v = *(const float4*)(hb + lb * 512 + k0 + kq + j * 4);
                hs[kq+j*4+0][lb]=v.x; hs[kq+j*4+1][lb]=v.y;
                hs[kq+j*4+2][lb]=v.z; hs[kq+j*4+3][lb]=v.w;
            }
            float4 v = *(const float4*)(W_hh + (size_t)(n0 + wn) * 512 + k0 + wq);
            ws[wq][wn]=v.x; ws[wq+1][wn]=v.y; ws[wq+2][wn]=v.z; ws[wq+3][wn]=v.w;
        } else {
            int k1 = k0 - 512;
#pragma unroll
            for (int j = 0; j < 4; j++) {
                float4 v = *(const float4*)(g_ctx + lb * 256 + k1 + kq + j * 4);
                hs[kq+j*4+0][lb]=v.x; hs[kq+j*4+1][lb]=v.y;
                hs[kq+j*4+2][lb]=v.z; hs[kq+j*4+3][lb]=v.w;
            }
            float4 v = *(const float4*)(W_ih + (size_t)(n0 + wn) * 768 + 512 + k1 + wq);
            ws[wq][wn]=v.x; ws[wq+1][wn]=v.y; ws[wq+2][wn]=v.z; ws[wq+3][wn]=v.w;
        }
        __syncthreads();
#pragma unroll 16
        for (int kk = 0; kk < 64; kk++) {
            float w = ws[kk][nl];
            unsigned long long w2 = pk2(w, w);
            fma2(acc0, *(const unsigned long long*)&hs[kk][bq*4],   w2);
            fma2(acc1, *(const unsigned long long*)&hs[kk][bq*4+2], w2);
        }
        __syncthreads();
    }
    int n = n0 + nl;
    const float* xr = g_xg + (size_t)t * 64 * GATES;
    float2 a = upk(acc0), b2 = upk(acc1);
    g_gates[(bq*4+0)*GATES+n] = xr[(bq*4+0)*GATES+n] + a.x;
    g_gates[(bq*4+1)*GATES+n] = xr[(bq*4+1)*GATES+n] + a.y;
    g_gates[(bq*4+2)*GATES+n] = xr[(bq*4+2)*GATES+n] + b2.x;
    g_gates[(bq*4+3)*GATES+n] = xr[(bq*4+3)*GATES+n] + b2.y;
}

// ---------------- per-step: LSTM pointwise ---------------------------------
__global__ void k_point(int t) {
    int idx = blockIdx.x * 256 + threadIdx.x;   // 0..32767
    int b = idx >> 9, d = idx & 511;
    const float* g = g_gates + b * GATES;
    float ig = g[d], fg = g[512 + d], gg = g[1024 + d], og = g[1536 + d];
    float c = g_c[idx];
    float cn = sigmoidf_(fg) * c + sigmoidf_(ig) * tanhf(gg);
    float hn = sigmoidf_(og) * tanhf(cn);
    g_c[idx] = cn;
    g_h[(t + 1) & 1][idx] = hn;
    g_Hall[((size_t)t * 64 + b) * 512 + d] = hn;
}

// ---------------- launch ----------------------------------------------------
extern "C" void kernel_launch(void* const* d_in, const int* in_sizes, int n_in,
                              void* d_out, int out_size) {
    const float* enc    = (const float*)d_in[0];
    const void*  caps   = d_in[1];
    const float* W_enc  = (const float*)d_in[2];
    const float* b_enc  = (const float*)d_in[3];
    const float* W_dec  = (const float*)d_in[4];
    const float* b_dec  = (const float*)d_in[5];
    const float* W_full = (const float*)d_in[6];
    // d_in[7] = b_full (softmax shift-invariant, unused)
    const float* emb    = (const float*)d_in[8];
    const float* W_ih   = (const float*)d_in[9];
    const float* b_ih   = (const float*)d_in[10];
    const float* W_hh   = (const float*)d_in[11];
    const float* b_hh   = (const float*)d_in[12];
    const float* W_fc   = (const float*)d_in[13];
    const float* b_fc   = (const float*)d_in[14];
    float* out = (float*)d_out;

    float *p_feats, *p_enc_att, *p_E, *p_xg, *p_bias2, *p_Hall;
    cudaGetSymbolAddress((void**)&p_feats,   g_feats);
    cudaGetSymbolAddress((void**)&p_enc_att, g_enc_att);
    cudaGetSymbolAddress((void**)&p_E,       g_E);
    cudaGetSymbolAddress((void**)&p_xg,      g_xg);
    cudaGetSymbolAddress((void**)&p_bias2,   g_bias2);
    cudaGetSymbolAddress((void**)&p_Hall,    g_Hall);

    k_init<<<264, 256>>>(b_ih, b_hh, caps);
    k_transpose<<<dim3(7, 8, 64), dim3(32, 8)>>>(enc);
    k_gather<<<T_STEPS * BATCH, 128>>>(caps, emb);
    // enc_att = feats @ W_enc + b_enc : [12544 x 512] @ [512-col, K=256]
    k_gemm<false, false><<<dim3(8, 98), 256>>>(p_feats, ENC_C, W_enc, ATT_D, b_enc,
                                               p_enc_att, ATT_D,
                                               BATCH * PIX, ATT_D, ENC_C);
    // xg = E @ W_ih[:, :512]^T + (b_ih + b_hh) : [1280 x 2048], K=512, ldb=768
    k_gemm<true, false><<<dim3(32, 10), 256>>>(p_E, EMB_D, W_ih, EMB_D + ENC_C, p_bias2,
                                               p_xg, GATES,
                                               T_STEPS * BATCH, GATES, EMB_D);
    for (int t = 0; t < T_STEPS; t++) {
        k_dec<<<32, 256>>>(W_dec, b_dec, t);
        k_att<<<BATCH, 256>>>(W_full, t);
        k_gates<<<128, 256>>>(W_hh, W_ih, t);
        k_point<<<128, 256>>>(t);
    }
    // out[b][t][:] = Hall @ W_fc + b_fc : [1280 x 30000], K=512 (row remap)
    k_gemm<false, true><<<dim3(469, 10), 256>>>(p_Hall, DEC_D, W_fc, VOCAB, b_fc,
                                                out, VOCAB,
                                                T_STEPS * BATCH, VOCAB, DEC_D);
}